// round 1
// baseline (speedup 1.0000x reference)
#include <cuda_runtime.h>

// GCBFSafetyLayer — analytical reduction:
//
// In the reference, dh_dx = [jac_pos, 0] (velocity half zero) and
// g = [[0],[I/MASS]] (position half zero), so
//   L_g_h = dh_dx @ g == 0  identically.
// The projection loop's update is gated by (||a||^2 > 1e-6), which is never
// true when A = L_g_h = 0, so u is never modified and
//   safe_action == raw_action  (bit-exact; no arithmetic touches u).
//
// Hence the kernel is an identity copy of d_in[3] (raw_action, 256*128*2
// floats = 256 KB) into d_out. We do it as a single vectorized float4 copy
// kernel (one graph node, launch-overhead bound).

__global__ void gcbf_identity_copy_kernel(const float4* __restrict__ src,
                                          float4* __restrict__ dst,
                                          int n_vec) {
    int i = blockIdx.x * blockDim.x + threadIdx.x;
    if (i < n_vec) {
        dst[i] = src[i];
    }
}

extern "C" void kernel_launch(void* const* d_in, const int* in_sizes, int n_in,
                              void* d_out, int out_size) {
    // Inputs (metadata order): positions, velocities, obstacles, raw_action
    const float* raw_action = (const float*)d_in[3];
    float* out = (float*)d_out;

    // out_size = 256*128*2 = 65536 floats; divisible by 4 -> float4 copy.
    int n_vec = out_size / 4;  // 16384 float4
    const int threads = 256;
    int blocks = (n_vec + threads - 1) / threads;  // 64
    gcbf_identity_copy_kernel<<<blocks, threads>>>(
        (const float4*)raw_action, (float4*)out, n_vec);
}